// round 11
// baseline (speedup 1.0000x reference)
#include <cuda_runtime.h>
#include <cuda_fp16.h>
#include <math.h>

// Radon transform: x (4,1,384,384) f32 -> out (4, 460, 64) f32
// pad=38, Hp=Wp=460, 64 angles at a*2.8125 deg.
//
// R10 = R9 (90-deg symmetry, fp16 quad scratch, dual layouts, block partials)
//  + FULL batch merge: interleaved quads [layout][QR][QC][pair] -> one warp
//    serves all 4 batches with 2 LDG.128/iter (coords amortized 4-way).
//  + j-split (2 halves per i-group) keeps 238K threads resident.
//  + prep re-tiled to 16x16 quads, 625 blocks, all batches+layouts per block.

#define IH 384
#define IW 384
#define PAD 38
#define HP 460
#define WP 460
#define NA 64
#define NB 4

#define QR 385
#define QC 392            // quad row stride: 392*32B = 98 x 128B lines
#define QBASE (PAD - 1)
#define NWB   115         // 4-i groups per angle
#define NWBG  29          // groups of 4 i-groups (16 i's per block)
#define NT2   25          // 16-quad tiles per axis (25*16 = 400 >= 385)

// 2 layouts * 385 * 392 * 2 pairs * 16B = 9.7 MB (.bss).
// quad[p] = { h2(b0.v00,v01), h2(b0.v10,v11), h2(b1.v00,v01), h2(b1.v10,v11) }
__device__ uint4 g_q[2][QR][QC][2];
// Column partials: [group][(b*32+a)*460 + j], 6.8 MB, fully rewritten.
__device__ float g_colpart[NWBG][NB * 32 * HP];

__device__ __forceinline__ unsigned packh2(float a, float b) {
    __half2 h = __floats2half2_rn(a, b);
    return *reinterpret_cast<unsigned*>(&h);
}

// One block per 16x16 quad tile; loads 4 batches' 17x17 image tile once,
// emits interleaved quads for BOTH layouts (transposed region reads same tile).
__global__ __launch_bounds__(256) void prep_kernel(const float* __restrict__ x) {
    __shared__ float sh[NB][17][17];

    int bid = blockIdx.x;
    int tc = bid % NT2;
    int tr = bid / NT2;

    int R0 = tr * 16 - 1;
    int C0 = tc * 16 - 1;

    for (int idx = threadIdx.x; idx < NB * 17 * 17; idx += 256) {
        int k  = idx / (17 * 17);
        int rc = idx - k * (17 * 17);
        int yy = rc / 17, xx = rc - yy * 17;
        int gy = R0 + yy, gx = C0 + xx;
        float v = 0.0f;
        if (((unsigned)gy < IH) & ((unsigned)gx < IW))
            v = __ldg(x + k * (IH * IW) + gy * IW + gx);
        sh[k][yy][xx] = v;
    }
    __syncthreads();

    int rl = threadIdx.x >> 4, cl = threadIdx.x & 15;

    // layout 0: quad(rr,cc) = img[rr-1..rr][cc-1..cc]
    {
        int rr = tr * 16 + rl, cc = tc * 16 + cl;
        if ((rr < QR) & (cc < QR)) {
            #pragma unroll
            for (int p = 0; p < 2; ++p) {
                uint4 v;
                v.x = packh2(sh[2*p][rl][cl],       sh[2*p][rl][cl + 1]);
                v.y = packh2(sh[2*p][rl + 1][cl],   sh[2*p][rl + 1][cl + 1]);
                v.z = packh2(sh[2*p+1][rl][cl],     sh[2*p+1][rl][cl + 1]);
                v.w = packh2(sh[2*p+1][rl + 1][cl], sh[2*p+1][rl + 1][cl + 1]);
                g_q[0][rr][cc][p] = v;
            }
        }
    }
    // layout 1 (transposed image): quad(RR,CC) with RR=tc*16+rl, CC=tr*16+cl
    {
        int RR = tc * 16 + rl, CC = tr * 16 + cl;
        if ((RR < QR) & (CC < QR)) {
            #pragma unroll
            for (int p = 0; p < 2; ++p) {
                uint4 v;
                v.x = packh2(sh[2*p][cl][rl],       sh[2*p][cl + 1][rl]);
                v.y = packh2(sh[2*p][cl][rl + 1],   sh[2*p][cl + 1][rl + 1]);
                v.z = packh2(sh[2*p+1][cl][rl],     sh[2*p+1][cl + 1][rl]);
                v.w = packh2(sh[2*p+1][cl][rl + 1], sh[2*p+1][cl + 1][rl + 1]);
                g_q[1][RR][CC][p] = v;
            }
        }
    }
}

__device__ __forceinline__ float lerp2(unsigned top, unsigned bot,
                                       float wC, float wR) {
    float2 t = __half22float2(*reinterpret_cast<const __half2*>(&top));
    float2 b = __half22float2(*reinterpret_cast<const __half2*>(&bot));
    float h0 = fmaf(wC, t.y - t.x, t.x);
    float h1 = fmaf(wC, b.y - b.x, b.x);
    return fmaf(wR, h1 - h0, h0);
}

// Block = (a<32, wgrp): 8 warps = 4 i-groups (wl) x 2 j-halves.
// Warp: i = (wgrp*4 + wl)*4 + isub, lane = isub*8 + jsub; j over its half.
// Each warp produces ALL 4 batches.
__global__ __launch_bounds__(256) void radon_kernel(float* __restrict__ out)
{
    __shared__ float colsh[NB][4][464];
    __shared__ float rowsh[NB][16][2];

    const int wgrp = blockIdx.x % NWBG;
    const int a    = blockIdx.x / NWBG;

    const int wid   = threadIdx.x >> 5;
    const int lane  = threadIdx.x & 31;
    const int wl    = wid & 3;
    const int jhalf = wid >> 2;
    const int wblk  = wgrp * 4 + wl;
    const bool valid = (wblk < NWB);

    const int isub = lane >> 3;
    const int jsub = lane & 7;
    const int i    = wblk * 4 + isub;
    const int il   = wl * 4 + isub;          // i_local in [0,16)

    float c, s;
    {
        float deg = 2.8125f * (float)a;
        float th  = deg * (float)(3.14159265358979323846 / 180.0);
        sincosf(th, &s, &c);
    }

    if (valid) {
        const float u  = (float)i - 229.5f;
        const float SH = 229.5f - (float)QBASE;

        const bool tmode = fabsf(c) > fabsf(s);
        const float Rv = tmode ? -s : c;
        const float Cv = tmode ?  c : -s;
        const float R0 = (tmode ? c * u : s * u) + SH;
        const float C0 = (tmode ? s * u : c * u) + SH;
        const uint4* __restrict__ base = &g_q[tmode ? 1 : 0][0][0][0];

        float acc0 = 0.f, acc1 = 0.f, acc2 = 0.f, acc3 = 0.f;
        const int j0 = jhalf * 232;
        float vf = (float)(j0 + jsub) - 229.5f;
        int   j  = j0 + jsub;

        // jhalf0: 29 full iters (j<232). jhalf1: 28 full + tail (j<460).
        #pragma unroll 4
        for (int it = 0; it < 28; ++it, vf += 8.0f, j += 8) {
            float R = fmaf(Rv, vf, R0);
            float C = fmaf(Cv, vf, C0);
            float Rf = floorf(R), Cf = floorf(C);
            float wR = R - Rf,    wC = C - Cf;
            int   rq = (int)Rf,   cq = (int)Cf;

            float v0 = 0.f, v1 = 0.f, v2 = 0.f, v3 = 0.f;
            if (((unsigned)rq < (unsigned)QR) & ((unsigned)cq < (unsigned)QR)) {
                const uint4* p = base + (rq * QC + cq) * 2;
                uint4 q0 = __ldg(p);
                uint4 q1 = __ldg(p + 1);
                v0 = lerp2(q0.x, q0.y, wC, wR);
                v1 = lerp2(q0.z, q0.w, wC, wR);
                v2 = lerp2(q1.x, q1.y, wC, wR);
                v3 = lerp2(q1.z, q1.w, wC, wR);
            }
            acc0 += v0; acc1 += v1; acc2 += v2; acc3 += v3;
            v0 += __shfl_xor_sync(0xffffffffu, v0, 8);
            v0 += __shfl_xor_sync(0xffffffffu, v0, 16);
            v1 += __shfl_xor_sync(0xffffffffu, v1, 8);
            v1 += __shfl_xor_sync(0xffffffffu, v1, 16);
            v2 += __shfl_xor_sync(0xffffffffu, v2, 8);
            v2 += __shfl_xor_sync(0xffffffffu, v2, 16);
            v3 += __shfl_xor_sync(0xffffffffu, v3, 8);
            v3 += __shfl_xor_sync(0xffffffffu, v3, 16);
            if (isub == 0) {
                colsh[0][wl][j] = v0; colsh[1][wl][j] = v1;
                colsh[2][wl][j] = v2; colsh[3][wl][j] = v3;
            }
        }
        {   // iteration 29: jhalf0 full (j=224..231); jhalf1 only jsub<4 (456..459)
            bool ok = (jhalf == 0) | (jsub < 4);
            float v0 = 0.f, v1 = 0.f, v2 = 0.f, v3 = 0.f;
            if (ok) {
                float R = fmaf(Rv, vf, R0);
                float C = fmaf(Cv, vf, C0);
                float Rf = floorf(R), Cf = floorf(C);
                float wR = R - Rf,    wC = C - Cf;
                int   rq = (int)Rf,   cq = (int)Cf;
                if (((unsigned)rq < (unsigned)QR) & ((unsigned)cq < (unsigned)QR)) {
                    const uint4* p = base + (rq * QC + cq) * 2;
                    uint4 q0 = __ldg(p);
                    uint4 q1 = __ldg(p + 1);
                    v0 = lerp2(q0.x, q0.y, wC, wR);
                    v1 = lerp2(q0.z, q0.w, wC, wR);
                    v2 = lerp2(q1.x, q1.y, wC, wR);
                    v3 = lerp2(q1.z, q1.w, wC, wR);
                }
            }
            acc0 += v0; acc1 += v1; acc2 += v2; acc3 += v3;
            v0 += __shfl_xor_sync(0xffffffffu, v0, 8);
            v0 += __shfl_xor_sync(0xffffffffu, v0, 16);
            v1 += __shfl_xor_sync(0xffffffffu, v1, 8);
            v1 += __shfl_xor_sync(0xffffffffu, v1, 16);
            v2 += __shfl_xor_sync(0xffffffffu, v2, 8);
            v2 += __shfl_xor_sync(0xffffffffu, v2, 16);
            v3 += __shfl_xor_sync(0xffffffffu, v3, 8);
            v3 += __shfl_xor_sync(0xffffffffu, v3, 16);
            if ((isub == 0) & ok) {
                colsh[0][wl][j] = v0; colsh[1][wl][j] = v1;
                colsh[2][wl][j] = v2; colsh[3][wl][j] = v3;
            }
        }

        // row partial: reduce each acc over the 8 jsub lanes
        #pragma unroll
        for (int off = 4; off; off >>= 1) {
            acc0 += __shfl_xor_sync(0xffffffffu, acc0, off);
            acc1 += __shfl_xor_sync(0xffffffffu, acc1, off);
            acc2 += __shfl_xor_sync(0xffffffffu, acc2, off);
            acc3 += __shfl_xor_sync(0xffffffffu, acc3, off);
        }
        if (jsub == 0) {
            rowsh[0][il][jhalf] = acc0;
            rowsh[1][il][jhalf] = acc1;
            rowsh[2][il][jhalf] = acc2;
            rowsh[3][il][jhalf] = acc3;
        }
    } else {
        // invalid warp (only wgrp=28, wl=3): zero its colsh range + rowsh rows
        const int j0 = jhalf * 232, j1 = jhalf ? 460 : 232;
        for (int j = j0 + lane; j < j1; j += 32) {
            colsh[0][wl][j] = 0.f; colsh[1][wl][j] = 0.f;
            colsh[2][wl][j] = 0.f; colsh[3][wl][j] = 0.f;
        }
        if (jsub == 0) {
            rowsh[0][il][jhalf] = 0.f; rowsh[1][il][jhalf] = 0.f;
            rowsh[2][il][jhalf] = 0.f; rowsh[3][il][jhalf] = 0.f;
        }
    }

    __syncthreads();

    // row outputs: 4 batches x 16 i_locals -> angle a+32
    if (threadIdx.x < NB * 16) {
        int b  = threadIdx.x >> 4;
        int il2 = threadIdx.x & 15;
        int ii = wgrp * 16 + il2;
        if (ii < 460) {
            float v = rowsh[b][il2][0] + rowsh[b][il2][1];
            out[(b * HP + (459 - ii)) * NA + (a + 32)] = v * (1.0f / (float)WP);
        }
    }

    // column partials: reduce 4 wl slices per (b, j)
    for (int t = threadIdx.x; t < NB * HP; t += 256) {
        int b = t / HP, j = t - b * HP;
        float sum = colsh[b][0][j] + colsh[b][1][j]
                  + colsh[b][2][j] + colsh[b][3][j];
        g_colpart[wgrp][(b * 32 + a) * HP + j] = sum;
    }
}

// Sum the 29 group partials per (b, a<32, j) -> angle a output.
__global__ __launch_bounds__(256) void combine_kernel(float* __restrict__ out)
{
    int t = blockIdx.x * blockDim.x + threadIdx.x;
    if (t >= NB * 32 * HP) return;
    float sum = 0.0f;
    #pragma unroll
    for (int g = 0; g < NWBG; ++g)
        sum += g_colpart[g][t];
    int j  = t % HP;
    int ba = t / HP;
    int a  = ba & 31;
    int b  = ba >> 5;
    out[(b * HP + j) * NA + a] = sum * (1.0f / (float)WP);
}

extern "C" void kernel_launch(void* const* d_in, const int* in_sizes, int n_in,
                              void* d_out, int out_size) {
    (void)in_sizes; (void)n_in; (void)out_size;
    const float* x = (const float*)d_in[0];
    float* out = (float*)d_out;

    prep_kernel<<<NT2 * NT2, 256>>>(x);            // 625 blocks

    radon_kernel<<<32 * NWBG, 256>>>(out);         // 928 blocks

    const int ncomb = NB * 32 * HP;                 // 58880
    combine_kernel<<<(ncomb + 255) / 256, 256>>>(out);
}

// round 12
// speedup vs baseline: 1.1131x; 1.1131x over previous
#include <cuda_runtime.h>
#include <cuda_fp16.h>
#include <math.h>

// Radon transform: x (4,1,384,384) f32 -> out (4, 460, 64) f32
// pad=38, Hp=Wp=460, 64 angles at a*2.8125 deg.
//
// R12: pair-packed scratch replaces quad-packed scratch.
// Evidence (R10 neutral): radon is bound by DISTINCT L1 BYTES per warp
// footprint, not by iteration/instruction count. Quad layout stored 32B per
// lattice point (4x pixel redundancy). Pair layout stores 16B per point:
//   g_p[layout][r][c] = { h2(b0: px[r][c],px[r][c+1]), b1, b2, b3 }
// Sample reads points (r,c) and (r+1,c): still 2 LDG.128/iter, but half the
// byte density -> ~half the L1 wavefronts. Rows 0 and 385 are stored zeros,
// so the single bounds check rq,cq in [0,384] covers both row loads.

#define IH 384
#define IW 384
#define PAD 38
#define HP 460
#define WP 460
#define NA 64
#define NB 4

#define QR 385            // valid floor-coord index range [0,384]
#define PR 386            // stored point rows 0..385
#define PC 392            // point row stride: 392*16B = 49 x 128B lines
#define QBASE (PAD - 1)
#define NWB   115         // 4-i groups per angle
#define NWBG  29          // groups of 4 i-groups (16 i's per block)
#define NT2   25          // 16-point tiles per axis (400 >= 386)

// 2 layouts * 386 * 392 * 16B = 4.84 MB (.bss).
__device__ uint4 g_p[2][PR][PC];
// Column partials: [group][(b*32+a)*460 + j], 6.8 MB, fully rewritten.
__device__ float g_colpart[NWBG][NB * 32 * HP];

__device__ __forceinline__ unsigned packh2(float a, float b) {
    __half2 h = __floats2half2_rn(a, b);
    return *reinterpret_cast<unsigned*>(&h);
}

// Point (rp,cp), layout 0: img row rp-1, cols cp-1, cp (0 outside [0,384)).
// Layout 1 (transposed): img rows cp-1, cp at col rp-1.
// One block per 16x16 point tile; one 17x17 image tile load serves both.
__global__ __launch_bounds__(256) void prep_kernel(const float* __restrict__ x) {
    __shared__ float sh[NB][17][17];

    int bid = blockIdx.x;
    int tc = bid % NT2;
    int tr = bid / NT2;

    int R0 = tr * 16 - 1;    // image row of sh[][0][.]
    int C0 = tc * 16 - 1;    // image col of sh[][.][0]

    for (int idx = threadIdx.x; idx < NB * 17 * 17; idx += 256) {
        int k  = idx / (17 * 17);
        int rc = idx - k * (17 * 17);
        int yy = rc / 17, xx = rc - yy * 17;
        int gy = R0 + yy, gx = C0 + xx;
        float v = 0.0f;
        if (((unsigned)gy < IH) & ((unsigned)gx < IW))
            v = __ldg(x + k * (IH * IW) + gy * IW + gx);
        sh[k][yy][xx] = v;
    }
    __syncthreads();

    int rl = threadIdx.x >> 4, cl = threadIdx.x & 15;

    // layout 0: point(rp,cp) = h2( img[rp-1][cp-1], img[rp-1][cp] )
    {
        int rp = tr * 16 + rl, cp = tc * 16 + cl;
        if ((rp < PR) & (cp < QR)) {
            uint4 v;
            v.x = packh2(sh[0][rl][cl], sh[0][rl][cl + 1]);
            v.y = packh2(sh[1][rl][cl], sh[1][rl][cl + 1]);
            v.z = packh2(sh[2][rl][cl], sh[2][rl][cl + 1]);
            v.w = packh2(sh[3][rl][cl], sh[3][rl][cl + 1]);
            g_p[0][rp][cp] = v;
        }
    }
    // layout 1: point(RP,CP) = h2( img[CP-1][RP-1], img[CP][RP-1] )
    // with RP = tc*16+rl, CP = tr*16+cl  (reads sh[cl][rl], sh[cl+1][rl])
    {
        int RP = tc * 16 + rl, CP = tr * 16 + cl;
        if ((RP < PR) & (CP < QR)) {
            uint4 v;
            v.x = packh2(sh[0][cl][rl], sh[0][cl + 1][rl]);
            v.y = packh2(sh[1][cl][rl], sh[1][cl + 1][rl]);
            v.z = packh2(sh[2][cl][rl], sh[2][cl + 1][rl]);
            v.w = packh2(sh[3][cl][rl], sh[3][cl + 1][rl]);
            g_p[1][RP][CP] = v;
        }
    }
}

__device__ __forceinline__ float lerp2(unsigned top, unsigned bot,
                                       float wC, float wR) {
    float2 t = __half22float2(*reinterpret_cast<const __half2*>(&top));
    float2 b = __half22float2(*reinterpret_cast<const __half2*>(&bot));
    float h0 = fmaf(wC, t.y - t.x, t.x);
    float h1 = fmaf(wC, b.y - b.x, b.x);
    return fmaf(wR, h1 - h0, h0);
}

// Block = (a<32, wgrp): 8 warps = 4 i-groups (wl) x 2 j-halves.
// Warp: i = (wgrp*4 + wl)*4 + isub, lane = isub*8 + jsub; j over its half.
// Each warp produces ALL 4 batches.
__global__ __launch_bounds__(256) void radon_kernel(float* __restrict__ out)
{
    __shared__ float colsh[NB][4][464];
    __shared__ float rowsh[NB][16][2];

    const int wgrp = blockIdx.x % NWBG;
    const int a    = blockIdx.x / NWBG;

    const int wid   = threadIdx.x >> 5;
    const int lane  = threadIdx.x & 31;
    const int wl    = wid & 3;
    const int jhalf = wid >> 2;
    const int wblk  = wgrp * 4 + wl;
    const bool valid = (wblk < NWB);

    const int isub = lane >> 3;
    const int jsub = lane & 7;
    const int i    = wblk * 4 + isub;
    const int il   = wl * 4 + isub;          // i_local in [0,16)

    float c, s;
    {
        float deg = 2.8125f * (float)a;
        float th  = deg * (float)(3.14159265358979323846 / 180.0);
        sincosf(th, &s, &c);
    }

    if (valid) {
        const float u  = (float)i - 229.5f;
        const float SH = 229.5f - (float)QBASE;

        const bool tmode = fabsf(c) > fabsf(s);
        const float Rv = tmode ? -s : c;
        const float Cv = tmode ?  c : -s;
        const float R0 = (tmode ? c * u : s * u) + SH;
        const float C0 = (tmode ? s * u : c * u) + SH;
        const uint4* __restrict__ base = &g_p[tmode ? 1 : 0][0][0];

        float acc0 = 0.f, acc1 = 0.f, acc2 = 0.f, acc3 = 0.f;
        const int j0 = jhalf * 232;
        float vf = (float)(j0 + jsub) - 229.5f;
        int   j  = j0 + jsub;

        // jhalf0: 29 full iters (j<232). jhalf1: 28 full + tail (j<460).
        #pragma unroll 4
        for (int it = 0; it < 28; ++it, vf += 8.0f, j += 8) {
            float R = fmaf(Rv, vf, R0);
            float C = fmaf(Cv, vf, C0);
            float Rf = floorf(R), Cf = floorf(C);
            float wR = R - Rf,    wC = C - Cf;
            int   rq = (int)Rf,   cq = (int)Cf;

            float v0 = 0.f, v1 = 0.f, v2 = 0.f, v3 = 0.f;
            if (((unsigned)rq < (unsigned)QR) & ((unsigned)cq < (unsigned)QR)) {
                const uint4* p = base + rq * PC + cq;
                uint4 P0 = __ldg(p);
                uint4 P1 = __ldg(p + PC);
                v0 = lerp2(P0.x, P1.x, wC, wR);
                v1 = lerp2(P0.y, P1.y, wC, wR);
                v2 = lerp2(P0.z, P1.z, wC, wR);
                v3 = lerp2(P0.w, P1.w, wC, wR);
            }
            acc0 += v0; acc1 += v1; acc2 += v2; acc3 += v3;
            v0 += __shfl_xor_sync(0xffffffffu, v0, 8);
            v0 += __shfl_xor_sync(0xffffffffu, v0, 16);
            v1 += __shfl_xor_sync(0xffffffffu, v1, 8);
            v1 += __shfl_xor_sync(0xffffffffu, v1, 16);
            v2 += __shfl_xor_sync(0xffffffffu, v2, 8);
            v2 += __shfl_xor_sync(0xffffffffu, v2, 16);
            v3 += __shfl_xor_sync(0xffffffffu, v3, 8);
            v3 += __shfl_xor_sync(0xffffffffu, v3, 16);
            if (isub == 0) {
                colsh[0][wl][j] = v0; colsh[1][wl][j] = v1;
                colsh[2][wl][j] = v2; colsh[3][wl][j] = v3;
            }
        }
        {   // iteration 29: jhalf0 full (j=224..231); jhalf1 only jsub<4 (456..459)
            bool ok = (jhalf == 0) | (jsub < 4);
            float v0 = 0.f, v1 = 0.f, v2 = 0.f, v3 = 0.f;
            if (ok) {
                float R = fmaf(Rv, vf, R0);
                float C = fmaf(Cv, vf, C0);
                float Rf = floorf(R), Cf = floorf(C);
                float wR = R - Rf,    wC = C - Cf;
                int   rq = (int)Rf,   cq = (int)Cf;
                if (((unsigned)rq < (unsigned)QR) & ((unsigned)cq < (unsigned)QR)) {
                    const uint4* p = base + rq * PC + cq;
                    uint4 P0 = __ldg(p);
                    uint4 P1 = __ldg(p + PC);
                    v0 = lerp2(P0.x, P1.x, wC, wR);
                    v1 = lerp2(P0.y, P1.y, wC, wR);
                    v2 = lerp2(P0.z, P1.z, wC, wR);
                    v3 = lerp2(P0.w, P1.w, wC, wR);
                }
            }
            acc0 += v0; acc1 += v1; acc2 += v2; acc3 += v3;
            v0 += __shfl_xor_sync(0xffffffffu, v0, 8);
            v0 += __shfl_xor_sync(0xffffffffu, v0, 16);
            v1 += __shfl_xor_sync(0xffffffffu, v1, 8);
            v1 += __shfl_xor_sync(0xffffffffu, v1, 16);
            v2 += __shfl_xor_sync(0xffffffffu, v2, 8);
            v2 += __shfl_xor_sync(0xffffffffu, v2, 16);
            v3 += __shfl_xor_sync(0xffffffffu, v3, 8);
            v3 += __shfl_xor_sync(0xffffffffu, v3, 16);
            if ((isub == 0) & ok) {
                colsh[0][wl][j] = v0; colsh[1][wl][j] = v1;
                colsh[2][wl][j] = v2; colsh[3][wl][j] = v3;
            }
        }

        // row partial: reduce each acc over the 8 jsub lanes
        #pragma unroll
        for (int off = 4; off; off >>= 1) {
            acc0 += __shfl_xor_sync(0xffffffffu, acc0, off);
            acc1 += __shfl_xor_sync(0xffffffffu, acc1, off);
            acc2 += __shfl_xor_sync(0xffffffffu, acc2, off);
            acc3 += __shfl_xor_sync(0xffffffffu, acc3, off);
        }
        if (jsub == 0) {
            rowsh[0][il][jhalf] = acc0;
            rowsh[1][il][jhalf] = acc1;
            rowsh[2][il][jhalf] = acc2;
            rowsh[3][il][jhalf] = acc3;
        }
    } else {
        // invalid warp (only wgrp=28, wl=3): zero its colsh range + rowsh rows
        const int j0 = jhalf * 232, j1 = jhalf ? 460 : 232;
        for (int j = j0 + lane; j < j1; j += 32) {
            colsh[0][wl][j] = 0.f; colsh[1][wl][j] = 0.f;
            colsh[2][wl][j] = 0.f; colsh[3][wl][j] = 0.f;
        }
        if (jsub == 0) {
            rowsh[0][il][jhalf] = 0.f; rowsh[1][il][jhalf] = 0.f;
            rowsh[2][il][jhalf] = 0.f; rowsh[3][il][jhalf] = 0.f;
        }
    }

    __syncthreads();

    // row outputs: 4 batches x 16 i_locals -> angle a+32
    if (threadIdx.x < NB * 16) {
        int b  = threadIdx.x >> 4;
        int il2 = threadIdx.x & 15;
        int ii = wgrp * 16 + il2;
        if (ii < 460) {
            float v = rowsh[b][il2][0] + rowsh[b][il2][1];
            out[(b * HP + (459 - ii)) * NA + (a + 32)] = v * (1.0f / (float)WP);
        }
    }

    // column partials: reduce 4 wl slices per (b, j)
    for (int t = threadIdx.x; t < NB * HP; t += 256) {
        int b = t / HP, j = t - b * HP;
        float sum = colsh[b][0][j] + colsh[b][1][j]
                  + colsh[b][2][j] + colsh[b][3][j];
        g_colpart[wgrp][(b * 32 + a) * HP + j] = sum;
    }
}

// Sum the 29 group partials per (b, a<32, j) -> angle a output.
__global__ __launch_bounds__(256) void combine_kernel(float* __restrict__ out)
{
    int t = blockIdx.x * blockDim.x + threadIdx.x;
    if (t >= NB * 32 * HP) return;
    float sum = 0.0f;
    #pragma unroll
    for (int g = 0; g < NWBG; ++g)
        sum += g_colpart[g][t];
    int j  = t % HP;
    int ba = t / HP;
    int a  = ba & 31;
    int b  = ba >> 5;
    out[(b * HP + j) * NA + a] = sum * (1.0f / (float)WP);
}

extern "C" void kernel_launch(void* const* d_in, const int* in_sizes, int n_in,
                              void* d_out, int out_size) {
    (void)in_sizes; (void)n_in; (void)out_size;
    const float* x = (const float*)d_in[0];
    float* out = (float*)d_out;

    prep_kernel<<<NT2 * NT2, 256>>>(x);            // 625 blocks

    radon_kernel<<<32 * NWBG, 256>>>(out);         // 928 blocks

    const int ncomb = NB * 32 * HP;                 // 58880
    combine_kernel<<<(ncomb + 255) / 256, 256>>>(out);
}